// round 6
// baseline (speedup 1.0000x reference)
#include <cuda_runtime.h>
#include <cuda_bf16.h>

// Fused AttentionRouting, single kernel. CTA = (b, h), 1024 threads, 221KB smem.
//   Pass A (n asc):  load u[:,n,:,h,:] chunk (64KB) -> smem, v via load-time
//                    register partials, c_raw[i][n][w] -> C_ALL (128KB smem).
//   Softmax:         per-thread (i,w) exact LSE over n, C_ALL := c (+bias).
//   Pass B (n desc): s[j][w] = sum_i u*c (u re-read, coalesced, L2-friendly),
//                    squash over j, store out.
// u read 1x from DRAM + ~0.5x (L2-assisted) re-read. No global scratch.

#define BB 4
#define II 32
#define NN 32
#define JJ 16
#define HH 32
#define WW 32
#define HW 1024
#define STRIDE_I 524288            // N*J*H*W
#define CHUNK   16384              // J*HW per (i): n-stride within an i row

// smem float offsets
#define OFF_U      0               // u_s   [32][16][32]  16384
#define OFF_C      16384           // c_all [32][32][32]  32768
#define OFF_VP     49152           // vpart [8][16][8]f4   4096
#define OFF_V      53248           // v_s   [16][32]        512
#define OFF_SP     53760           // s_part[2][16][32]    1024
#define OFF_SS     54784           // s_s   [16][32]        512
#define SMEM_FLOATS 55296          // 221184 bytes

__global__ void __launch_bounds__(1024, 1)
fused_routing(const float* __restrict__ u, const float* __restrict__ bias,
              float* __restrict__ out) {
    extern __shared__ float sm[];

    const int bid = blockIdx.x;                  // b*32 + h
    const int h = bid & 31;
    const int b = bid >> 5;
    const int t = threadIdx.x;

    // pass-A load mapping: q = float4-in-row, jl = j, i8 = i mod-8 group
    const int q  = t & 7;
    const int jl = (t >> 3) & 15;
    const int i8 = t >> 7;                       // 0..7
    // (i,w) mapping for c_raw / softmax
    const int w  = t & 31;
    const int iA = t >> 5;                       // 0..31
    // pass-B mapping: (ih, jB, w)
    const int jB = (t >> 5) & 15;
    const int ih = t >> 9;                       // 0..1

    const size_t ubase = (size_t)b * II * STRIDE_I + (size_t)h * WW;
    // u element (i,n,j,w') = ubase + i*STRIDE_I + n*CHUNK + j*HW + w'

    // ---------------- Pass A ----------------
    const float* p0 = u + ubase + (size_t)i8 * STRIDE_I + jl * HW + q * 4;
    float4 r0 = *(const float4*)(p0);
    float4 r1 = *(const float4*)(p0 + (size_t)8  * STRIDE_I);
    float4 r2 = *(const float4*)(p0 + (size_t)16 * STRIDE_I);
    float4 r3 = *(const float4*)(p0 + (size_t)24 * STRIDE_I);

    for (int n = 0; n < NN; n++) {
        // P1: stage chunk n + v partials (4 i's per thread, in registers)
        *(float4*)(sm + OFF_U + ((i8     ) * JJ + jl) * WW + q * 4) = r0;
        *(float4*)(sm + OFF_U + ((i8 +  8) * JJ + jl) * WW + q * 4) = r1;
        *(float4*)(sm + OFF_U + ((i8 + 16) * JJ + jl) * WW + q * 4) = r2;
        *(float4*)(sm + OFF_U + ((i8 + 24) * JJ + jl) * WW + q * 4) = r3;
        float4 vp;
        vp.x = r0.x + r1.x + r2.x + r3.x;
        vp.y = r0.y + r1.y + r2.y + r3.y;
        vp.z = r0.z + r1.z + r2.z + r3.z;
        vp.w = r0.w + r1.w + r2.w + r3.w;
        *(float4*)(sm + OFF_VP + ((i8 * JJ + jl) * 8 + q) * 4) = vp;
        __syncthreads();

        // prefetch chunk n+1 into registers (overlaps P2/P3)
        if (n + 1 < NN) {
            const float* p = u + ubase + (size_t)i8 * STRIDE_I
                           + (size_t)(n + 1) * CHUNK + jl * HW + q * 4;
            r0 = *(const float4*)(p);
            r1 = *(const float4*)(p + (size_t)8  * STRIDE_I);
            r2 = *(const float4*)(p + (size_t)16 * STRIDE_I);
            r3 = *(const float4*)(p + (size_t)24 * STRIDE_I);
        }

        // P2: combine 8 i-groups -> v_s[j][w]
        if (t < 128) {
            const int j2 = t >> 3, q2 = t & 7;
            float4 a = make_float4(0.f, 0.f, 0.f, 0.f);
#pragma unroll
            for (int g = 0; g < 8; g++) {
                const float4 x =
                    *(const float4*)(sm + OFF_VP + ((g * JJ + j2) * 8 + q2) * 4);
                a.x += x.x; a.y += x.y; a.z += x.z; a.w += x.w;
            }
            *(float4*)(sm + OFF_V + j2 * WW + q2 * 4) = a;
        }
        __syncthreads();

        // P3: c_raw[iA][n][w] = sum_j u_s * v_s
        float acc = 0.f;
#pragma unroll
        for (int j = 0; j < JJ; j++)
            acc += sm[OFF_U + (iA * JJ + j) * WW + w] * sm[OFF_V + j * WW + w];
        sm[OFF_C + iA * 1024 + n * WW + w] = acc;
        __syncthreads();                          // u_s reused next n
    }

    // ---------------- Softmax over n (thread (iA,w)) ----------------
    {
        const int cb = OFF_C + iA * 1024 + w;
        float m = -3.402823466e+38f;
#pragma unroll
        for (int n = 0; n < NN; n++) m = fmaxf(m, sm[cb + n * WW]);
        m *= 0.25f;
        float s = 0.f;
#pragma unroll
        for (int n = 0; n < NN; n++)
            s += __expf(0.25f * sm[cb + n * WW] - m);
        const float lse = m + __logf(s);
#pragma unroll
        for (int n = 0; n < NN; n++)
            sm[cb + n * WW] = __expf(0.25f * sm[cb + n * WW] - lse)
                              + __ldg(&bias[iA * NN + n]);
    }
    __syncthreads();

    // ---------------- Pass B (n descending for L2 reuse) ----------------
    for (int n = NN - 1; n >= 0; n--) {
        // partial s over 16 i's: thread (ih, jB, w)
        const float* pb = u + ubase + (size_t)(ih * 16) * STRIDE_I
                        + (size_t)n * CHUNK + jB * HW + w;
        const int cbb = OFF_C + (ih * 16) * 1024 + n * WW + w;
        float a0 = 0.f, a1 = 0.f, a2 = 0.f, a3 = 0.f;
#pragma unroll
        for (int i2 = 0; i2 < 16; i2 += 4) {
            a0 += pb[(size_t)(i2 + 0) * STRIDE_I] * sm[cbb + (i2 + 0) * 1024];
            a1 += pb[(size_t)(i2 + 1) * STRIDE_I] * sm[cbb + (i2 + 1) * 1024];
            a2 += pb[(size_t)(i2 + 2) * STRIDE_I] * sm[cbb + (i2 + 2) * 1024];
            a3 += pb[(size_t)(i2 + 3) * STRIDE_I] * sm[cbb + (i2 + 3) * 1024];
        }
        sm[OFF_SP + (ih * JJ + jB) * WW + w] = (a0 + a1) + (a2 + a3);
        __syncthreads();

        float sv = 0.f;
        if (t < 512) {                            // (jB, w)
            sv = sm[OFF_SP + t] + sm[OFF_SP + 512 + t];
            sm[OFF_SS + t] = sv;
        }
        __syncthreads();

        if (t < 512) {
            float nrm2 = 0.f;
#pragma unroll
            for (int j2 = 0; j2 < JJ; j2++) {
                const float x = sm[OFF_SS + j2 * WW + w];
                nrm2 += x * x;
            }
            const float nrm = sqrtf(nrm2);
            const float factor =
                (1.0f - 1.0f / (__expf(nrm) + 1e-20f)) / (nrm + 1e-20f);
            out[((size_t)(b * NN + n) * JJ + (t >> 5)) * HW + h * WW + w] =
                sv * factor;
        }
        __syncthreads();                          // s_part/s_s reuse
    }
}

// ---------------------------------------------------------------------------
extern "C" void kernel_launch(void* const* d_in, const int* in_sizes, int n_in,
                              void* d_out, int out_size) {
    const float* u = (const float*)d_in[0];
    const float* bias = (const float*)d_in[1];
    float* out = (float*)d_out;

    cudaFuncSetAttribute(fused_routing,
                         cudaFuncAttributeMaxDynamicSharedMemorySize,
                         SMEM_FLOATS * (int)sizeof(float));   // 221184 B

    fused_routing<<<BB * HH, 1024, SMEM_FLOATS * sizeof(float)>>>(u, bias, out);
}

// round 7
// speedup vs baseline: 1.3737x; 1.3737x over previous
#include <cuda_runtime.h>
#include <cuda_bf16.h>

// AttentionRouting: u [B=4, I=32, N=32, J=16, H=32, W=32] f32, bias [1,32,32,1,1,1]
//   v = sum_i u; c_raw = sum_j u*v; c = softmax_n(0.25*c_raw) + bias
//   s = sum_i u*c; squash over j.
//
// R7: K1 lean reduction — j in 2 register-resident groups of 8 (MLP=8),
// per j: 8 shfl (4-i intra-warp) -> 1KB vpart -> 64-thread stage-2 ->
// broadcast LDS of v. 4 barriers/CTA, half the MIO of R5. K2/K3 as R5.

#define BB 4
#define II 32
#define NN 32
#define JJ 16
#define HH 32
#define WW 32
#define HW 1024
#define STRIDE_I 524288   // N*J*H*W

// scratch: c_raw [B,I,N,H,W] 16MB, lse [B,I,H,W] 512KB
__device__ float g_craw[BB * II * NN * HW];
__device__ float g_lse[BB * II * HW];

// ---------------------------------------------------------------------------
// K1: CTA = (b,n,h). 256 threads: i = tid>>3, q = tid&7 (w float4-chunk).
// ---------------------------------------------------------------------------
__global__ void __launch_bounds__(256, 5) k1_craw(const float* __restrict__ u) {
    __shared__ float4 vpart[8][8][8];              // [ig][jl][q] 8 KB
    __shared__ float v_s[8][32];                   // 1 KB

    const int bid = blockIdx.x;                    // (b*NN + n)*HH + h
    const int h = bid & 31;
    const int n = (bid >> 5) & 31;
    const int b = bid >> 10;
    const int tid = threadIdx.x;
    const int lane = tid & 31;
    const int warp = tid >> 5;
    const int q = lane & 7;
    const int iA = lane >> 3;                      // 0..3
    const int i = warp * 4 + iA;                   // 0..31

    const float* up = u + ((size_t)((b * II + i) * NN + n)) * (JJ * HW)
                        + h * WW + q * 4;

    float4 cacc = make_float4(0.f, 0.f, 0.f, 0.f);

#pragma unroll
    for (int g = 0; g < 2; g++) {
        // front-batched loads: 8 independent LDG.128
        float4 r[8];
#pragma unroll
        for (int jl = 0; jl < 8; jl++)
            r[jl] = *(const float4*)(up + (g * 8 + jl) * HW);

        // stage 1: intra-warp reduce over 4 i's (iA)
#pragma unroll
        for (int jl = 0; jl < 8; jl++) {
            float4 vp = r[jl];
            vp.x += __shfl_xor_sync(0xffffffffu, vp.x, 8);
            vp.y += __shfl_xor_sync(0xffffffffu, vp.y, 8);
            vp.z += __shfl_xor_sync(0xffffffffu, vp.z, 8);
            vp.w += __shfl_xor_sync(0xffffffffu, vp.w, 8);
            vp.x += __shfl_xor_sync(0xffffffffu, vp.x, 16);
            vp.y += __shfl_xor_sync(0xffffffffu, vp.y, 16);
            vp.z += __shfl_xor_sync(0xffffffffu, vp.z, 16);
            vp.w += __shfl_xor_sync(0xffffffffu, vp.w, 16);
            if (iA == 0) vpart[warp][jl][q] = vp;
        }
        __syncthreads();

        // stage 2: 64 threads combine 8 i-groups -> v_s[jl][w]
        if (tid < 64) {
            const int j2 = tid >> 3, q2 = tid & 7;
            float4 a = vpart[0][j2][q2];
#pragma unroll
            for (int ig = 1; ig < 8; ig++) {
                const float4 x = vpart[ig][j2][q2];
                a.x += x.x; a.y += x.y; a.z += x.z; a.w += x.w;
            }
            *(float4*)&v_s[j2][q2 * 4] = a;
        }
        __syncthreads();

        // compute: cacc += u_reg * v (broadcast LDS.128)
#pragma unroll
        for (int jl = 0; jl < 8; jl++) {
            const float4 v4 = *(const float4*)&v_s[jl][q * 4];
            cacc.x += r[jl].x * v4.x;
            cacc.y += r[jl].y * v4.y;
            cacc.z += r[jl].z * v4.z;
            cacc.w += r[jl].w * v4.w;
        }
        // next group's stage-1 writes to vpart happen after this group's
        // stage-2 reads (all threads passed 2nd barrier); v_s reads above
        // precede next stage-2 writes (separated by next 1st barrier).
    }

    *(float4*)(g_craw + ((size_t)((b * II + i) * NN + n)) * HW
               + h * WW + q * 4) = cacc;
}

// ---------------------------------------------------------------------------
// K2: per-pixel (b,i,h,w) log-sum-exp over n of 0.25*c_raw.
// ---------------------------------------------------------------------------
__global__ void __launch_bounds__(256) k2_lse() {
    const int t = blockIdx.x * 256 + threadIdx.x;  // 0..131071
    const int hw = t & 1023;
    const int bi = t >> 10;                        // b*II + i
    const float* p = g_craw + bi * (NN * HW) + hw;

    float vals[NN];
    float m = -3.402823466e+38f;
#pragma unroll
    for (int n = 0; n < NN; n++) {
        vals[n] = 0.25f * p[n * HW];
        m = fmaxf(m, vals[n]);
    }
    float s = 0.f;
#pragma unroll
    for (int n = 0; n < NN; n++) s += expf(vals[n] - m);
    g_lse[t] = m + logf(s);
}

// ---------------------------------------------------------------------------
// K3: per (b, n, h) slice, 512 threads (j,w). (b,n) REVERSED so early CTAs
// hit the u tail K1 left in L2.
// ---------------------------------------------------------------------------
__global__ void __launch_bounds__(512) k3_out(const float* __restrict__ u,
                                             const float* __restrict__ bias,
                                             float* __restrict__ out) {
    __shared__ float c_s[II * WW];                 // 4 KB
    __shared__ float s_s[JJ * WW];                 // 2 KB

    const int bid = blockIdx.x;                    // reversed mapping
    const int h = bid & 31;
    const int n = 31 - ((bid >> 5) & 31);
    const int b = (BB - 1) - (bid >> 10);
    const int tid = threadIdx.x;

#pragma unroll
    for (int t = tid; t < II * WW; t += 512) {
        const int i = t >> 5;
        const int w = t & 31;
        const int hw = h * WW + w;
        const float cr = g_craw[((b * II + i) * NN + n) * HW + hw];
        const float lse = g_lse[(b * II + i) * HW + hw];
        c_s[t] = expf(0.25f * cr - lse) + __ldg(&bias[i * NN + n]);
    }
    __syncthreads();

    const int jj = tid >> 5;                       // 0..15
    const int w = tid & 31;
    const int base = (b * 1024 + n) * (JJ * HW) + h * WW + w + jj * HW;

    float a0 = 0.f, a1 = 0.f, a2 = 0.f, a3 = 0.f;
#pragma unroll
    for (int i = 0; i < II; i += 4) {
        a0 += u[base + (i + 0) * STRIDE_I] * c_s[(i + 0) * 32 + w];
        a1 += u[base + (i + 1) * STRIDE_I] * c_s[(i + 1) * 32 + w];
        a2 += u[base + (i + 2) * STRIDE_I] * c_s[(i + 2) * 32 + w];
        a3 += u[base + (i + 3) * STRIDE_I] * c_s[(i + 3) * 32 + w];
    }
    const float acc = (a0 + a1) + (a2 + a3);

    s_s[tid] = acc;
    __syncthreads();

    float nrm2 = 0.f;
#pragma unroll
    for (int j2 = 0; j2 < JJ; j2++) {
        const float x = s_s[j2 * WW + w];
        nrm2 += x * x;
    }
    const float nrm = sqrtf(nrm2);
    const float factor =
        (1.0f - 1.0f / (expf(nrm) + 1e-20f)) / (nrm + 1e-20f);

    out[((b * NN + n) * JJ + jj) * HW + h * WW + w] = acc * factor;
}

// ---------------------------------------------------------------------------
extern "C" void kernel_launch(void* const* d_in, const int* in_sizes, int n_in,
                              void* d_out, int out_size) {
    const float* u = (const float*)d_in[0];
    const float* bias = (const float*)d_in[1];
    float* out = (float*)d_out;

    k1_craw<<<BB * NN * HH, 256>>>(u);             // 4096 CTAs
    k2_lse<<<(BB * II * HW) / 256, 256>>>();       // 512 CTAs
    k3_out<<<BB * NN * HH, 512>>>(u, bias, out);   // 4096 CTAs
}

// round 8
// speedup vs baseline: 1.4023x; 1.0208x over previous
#include <cuda_runtime.h>
#include <cuda_bf16.h>

// AttentionRouting: u [B=4, I=32, N=32, J=16, H=32, W=32] f32, bias [1,32,32,1,1,1]
//   v = sum_i u; c_raw = sum_j u*v; c = softmax_n(0.25*c_raw) + bias
//   s = sum_i u*c; squash over j.
//
// R8: K1 stage-1 reduced to ONE shfl level (4 shfl/j, 64/thread total);
// stage-2 (64 threads) combines 16 partials/warp-pair via LDS.128.
// Same load structure (j-groups of 8, MLP=8), 4 barriers. K2/K3 as R7.

#define BB 4
#define II 32
#define NN 32
#define JJ 16
#define HH 32
#define WW 32
#define HW 1024
#define STRIDE_I 524288   // N*J*H*W

// scratch: c_raw [B,I,N,H,W] 16MB, lse [B,I,H,W] 512KB
__device__ float g_craw[BB * II * NN * HW];
__device__ float g_lse[BB * II * HW];

// ---------------------------------------------------------------------------
// K1: CTA = (b,n,h). 256 threads: i = tid>>3, q = tid&7 (w float4-chunk).
// ---------------------------------------------------------------------------
__global__ void __launch_bounds__(256, 5) k1_craw(const float* __restrict__ u) {
    __shared__ float4 vpart[8][2][8][8];           // [warp][half][jl][q] 16 KB
    __shared__ float v_s[8][32];                   // 1 KB

    const int bid = blockIdx.x;                    // (b*NN + n)*HH + h
    const int h = bid & 31;
    const int n = (bid >> 5) & 31;
    const int b = bid >> 10;
    const int tid = threadIdx.x;
    const int lane = tid & 31;
    const int warp = tid >> 5;
    const int q = lane & 7;
    const int iA = lane >> 3;                      // 0..3
    const int i = warp * 4 + iA;                   // 0..31

    const float* up = u + ((size_t)((b * II + i) * NN + n)) * (JJ * HW)
                        + h * WW + q * 4;

    float4 cacc = make_float4(0.f, 0.f, 0.f, 0.f);

#pragma unroll
    for (int g = 0; g < 2; g++) {
        // front-batched loads: 8 independent LDG.128
        float4 r[8];
#pragma unroll
        for (int jl = 0; jl < 8; jl++)
            r[jl] = *(const float4*)(up + (g * 8 + jl) * HW);

        // stage 1: ONE xor level — pairs of i summed; halves iA={0,1},{2,3}
#pragma unroll
        for (int jl = 0; jl < 8; jl++) {
            float4 vp = r[jl];
            vp.x += __shfl_xor_sync(0xffffffffu, vp.x, 8);
            vp.y += __shfl_xor_sync(0xffffffffu, vp.y, 8);
            vp.z += __shfl_xor_sync(0xffffffffu, vp.z, 8);
            vp.w += __shfl_xor_sync(0xffffffffu, vp.w, 8);
            if ((iA & 1) == 0) vpart[warp][iA >> 1][jl][q] = vp;
        }
        __syncthreads();

        // stage 2: 64 threads combine 8 warps x 2 halves -> v_s[jl][w]
        if (tid < 64) {
            const int j2 = tid >> 3, q2 = tid & 7;
            float4 a = make_float4(0.f, 0.f, 0.f, 0.f);
#pragma unroll
            for (int wg = 0; wg < 8; wg++) {
#pragma unroll
                for (int hh = 0; hh < 2; hh++) {
                    const float4 x = vpart[wg][hh][j2][q2];
                    a.x += x.x; a.y += x.y; a.z += x.z; a.w += x.w;
                }
            }
            *(float4*)&v_s[j2][q2 * 4] = a;
        }
        __syncthreads();

        // compute: cacc += u_reg * v (broadcast LDS.128)
#pragma unroll
        for (int jl = 0; jl < 8; jl++) {
            const float4 v4 = *(const float4*)&v_s[jl][q * 4];
            cacc.x += r[jl].x * v4.x;
            cacc.y += r[jl].y * v4.y;
            cacc.z += r[jl].z * v4.z;
            cacc.w += r[jl].w * v4.w;
        }
    }

    *(float4*)(g_craw + ((size_t)((b * II + i) * NN + n)) * HW
               + h * WW + q * 4) = cacc;
}

// ---------------------------------------------------------------------------
// K2: per-pixel (b,i,h,w) log-sum-exp over n of 0.25*c_raw.
// ---------------------------------------------------------------------------
__global__ void __launch_bounds__(256) k2_lse() {
    const int t = blockIdx.x * 256 + threadIdx.x;  // 0..131071
    const int hw = t & 1023;
    const int bi = t >> 10;                        // b*II + i
    const float* p = g_craw + bi * (NN * HW) + hw;

    float vals[NN];
    float m = -3.402823466e+38f;
#pragma unroll
    for (int n = 0; n < NN; n++) {
        vals[n] = 0.25f * p[n * HW];
        m = fmaxf(m, vals[n]);
    }
    float s = 0.f;
#pragma unroll
    for (int n = 0; n < NN; n++) s += expf(vals[n] - m);
    g_lse[t] = m + logf(s);
}

// ---------------------------------------------------------------------------
// K3: per (b, n, h) slice, 512 threads (j,w). (b,n) REVERSED so early CTAs
// hit the u tail K1 left in L2.
// ---------------------------------------------------------------------------
__global__ void __launch_bounds__(512) k3_out(const float* __restrict__ u,
                                             const float* __restrict__ bias,
                                             float* __restrict__ out) {
    __shared__ float c_s[II * WW];                 // 4 KB
    __shared__ float s_s[JJ * WW];                 // 2 KB

    const int bid = blockIdx.x;                    // reversed mapping
    const int h = bid & 31;
    const int n = 31 - ((bid >> 5) & 31);
    const int b = (BB - 1) - (bid >> 10);
    const int tid = threadIdx.x;

#pragma unroll
    for (int t = tid; t < II * WW; t += 512) {
        const int i = t >> 5;
        const int w = t & 31;
        const int hw = h * WW + w;
        const float cr = g_craw[((b * II + i) * NN + n) * HW + hw];
        const float lse = g_lse[(b * II + i) * HW + hw];
        c_s[t] = expf(0.25f * cr - lse) + __ldg(&bias[i * NN + n]);
    }
    __syncthreads();

    const int jj = tid >> 5;                       // 0..15
    const int w = tid & 31;
    const int base = (b * 1024 + n) * (JJ * HW) + h * WW + w + jj * HW;

    float a0 = 0.f, a1 = 0.f, a2 = 0.f, a3 = 0.f;
#pragma unroll
    for (int i = 0; i < II; i += 4) {
        a0 += u[base + (i + 0) * STRIDE_I] * c_s[(i + 0) * 32 + w];
        a1 += u[base + (i + 1) * STRIDE_I] * c_s[(i + 1) * 32 + w];
        a2 += u[base + (i + 2) * STRIDE_I] * c_s[(i + 2) * 32 + w];
        a3 += u[base + (i + 3) * STRIDE_I] * c_s[(i + 3) * 32 + w];
    }
    const float acc = (a0 + a1) + (a2 + a3);

    s_s[tid] = acc;
    __syncthreads();

    float nrm2 = 0.f;
#pragma unroll
    for (int j2 = 0; j2 < JJ; j2++) {
        const float x = s_s[j2 * WW + w];
        nrm2 += x * x;
    }
    const float nrm = sqrtf(nrm2);
    const float factor =
        (1.0f - 1.0f / (expf(nrm) + 1e-20f)) / (nrm + 1e-20f);

    out[((b * NN + n) * JJ + jj) * HW + h * WW + w] = acc * factor;
}

// ---------------------------------------------------------------------------
extern "C" void kernel_launch(void* const* d_in, const int* in_sizes, int n_in,
                              void* d_out, int out_size) {
    const float* u = (const float*)d_in[0];
    const float* bias = (const float*)d_in[1];
    float* out = (float*)d_out;

    k1_craw<<<BB * NN * HH, 256>>>(u);             // 4096 CTAs
    k2_lse<<<(BB * II * HW) / 256, 256>>>();       // 512 CTAs
    k3_out<<<BB * NN * HH, 512>>>(u, bias, out);   // 4096 CTAs
}